// round 1
// baseline (speedup 1.0000x reference)
#include <cuda_runtime.h>
#include <cuda_bf16.h>

// Problem constants
#define B 4
#define P 12000
#define C 64
#define H 512
#define W 512
#define TILE_X 128

// Scratch: winner pillar index per output pixel (-1 = empty). 4 MB.
__device__ int g_winner[B * H * W];

// Kernel A: reset winner map every launch (graph-replay safe).
__global__ void init_winner_kernel() {
    int i = blockIdx.x * blockDim.x + threadIdx.x;
    if (i < B * H * W) g_winner[i] = -1;
}

// Kernel B: one thread per (b, p). Last update wins in the reference
// (sequential scatter-set), i.e. the LARGEST p wins -> atomicMax.
__global__ void scatter_winner_kernel(const int* __restrict__ coords) {
    int i = blockIdx.x * blockDim.x + threadIdx.x;   // i = b*P + p
    if (i >= B * P) return;
    int b = i / P;
    int p = i - b * P;
    // coords[b][p][0..3] = (batch, y, x, z); 16B-aligned vector load.
    int4 c4 = reinterpret_cast<const int4*>(coords)[i];
    int y = c4.y;
    int x = c4.z;
    if ((unsigned)x < (unsigned)W && (unsigned)y < (unsigned)H) {
        atomicMax(&g_winner[(b * H + y) * W + x], p);
    }
}

// Kernel C: gather pass. One block per (b, y, 128-wide x tile).
// Loads the 128 winner entries once into smem, then writes all 64 channels
// as coalesced float4 stores. 256 threads, 8 iterations of 256 float4 each.
__global__ __launch_bounds__(256) void gather_out_kernel(
    const float* __restrict__ feat, float* __restrict__ out) {
    __shared__ int s_win[TILE_X];

    const int b  = blockIdx.z;
    const int y  = blockIdx.y;
    const int x0 = blockIdx.x * TILE_X;
    const int tid = threadIdx.x;

    if (tid < TILE_X) {
        s_win[tid] = g_winner[(b * H + y) * W + x0 + tid];
    }
    __syncthreads();

    const int QUADS = TILE_X / 4;           // 32 float4 per channel row
    const int UNITS = C * QUADS;            // 2048 float4 per block

    const float* featb = feat + (size_t)b * P * C;
    // base float4 index of out[b][0][y][x0]
    const size_t out_q_base = ((((size_t)b * C) * H + y) * W + x0) >> 2;
    const size_t c_stride_q = (size_t)H * W >> 2;   // float4 stride between channels

    #pragma unroll
    for (int it = 0; it < UNITS / 256; ++it) {
        int u  = it * 256 + tid;
        int c  = u / QUADS;
        int xq = u - c * QUADS;

        int p0 = s_win[xq * 4 + 0];
        int p1 = s_win[xq * 4 + 1];
        int p2 = s_win[xq * 4 + 2];
        int p3 = s_win[xq * 4 + 3];

        float4 v;
        v.x = (p0 >= 0) ? featb[(size_t)p0 * C + c] : 0.0f;
        v.y = (p1 >= 0) ? featb[(size_t)p1 * C + c] : 0.0f;
        v.z = (p2 >= 0) ? featb[(size_t)p2 * C + c] : 0.0f;
        v.w = (p3 >= 0) ? featb[(size_t)p3 * C + c] : 0.0f;

        reinterpret_cast<float4*>(out)[out_q_base + (size_t)c * c_stride_q + xq] = v;
    }
}

extern "C" void kernel_launch(void* const* d_in, const int* in_sizes, int n_in,
                              void* d_out, int out_size) {
    const float* feat   = (const float*)d_in[0];   // [B, P, C] fp32
    const int*   coords = (const int*)d_in[1];     // [B, P, 4] int32
    float* out = (float*)d_out;                    // [B, C, H, W] fp32

    init_winner_kernel<<<(B * H * W + 255) / 256, 256>>>();
    scatter_winner_kernel<<<(B * P + 255) / 256, 256>>>(coords);

    dim3 grid(W / TILE_X, H, B);   // (4, 512, 4) = 8192 blocks
    gather_out_kernel<<<grid, 256>>>(feat, out);
}

// round 2
// speedup vs baseline: 1.3192x; 1.3192x over previous
#include <cuda_runtime.h>
#include <cuda_bf16.h>

// Problem constants
#define B 4
#define P 12000
#define C 64
#define H 512
#define W 512
#define TILE_X 128

// Winner pillar map per output pixel, encoded as (p+1); 0 = empty.
// Zero-initialized at module load; gather kernel restores its strip to 0,
// so the all-zeros invariant holds before every kernel_launch call.
__device__ int g_winner[B * H * W];

// Kernel 1: one thread per (b, p). Reference semantics: sequential .at[].set
// means the LARGEST pillar index wins per pixel -> atomicMax on (p+1).
__global__ void scatter_winner_kernel(const int* __restrict__ coords) {
    int i = blockIdx.x * blockDim.x + threadIdx.x;   // i = b*P + p
    if (i >= B * P) return;
    int b = i / P;
    int p = i - b * P;
    int4 c4 = reinterpret_cast<const int4*>(coords)[i];  // (batch, y, x, z)
    int y = c4.y;
    int x = c4.z;
    if ((unsigned)x < (unsigned)W && (unsigned)y < (unsigned)H) {
        atomicMax(&g_winner[(b * H + y) * W + x], p + 1);
    }
}

// Kernel 2: gather + emit. One block per (b, y, 128-wide x tile).
//  - load 128 winner entries into smem, reset them to 0 in gmem
//  - compact occupied pixels into slots, stage their feature rows in smem
//  - emit all 64 channels as streaming float4 stores fed purely from smem
__global__ __launch_bounds__(256) void gather_out_kernel(
    const float* __restrict__ feat, float* __restrict__ out) {
    __shared__ int   s_win[TILE_X];
    __shared__ int   s_slot[TILE_X];    // slot id or -1
    __shared__ int   s_pid[TILE_X];     // slot -> pillar index
    __shared__ int   s_n;
    __shared__ float s_feat[TILE_X * 65];  // padded rows: distinct slots -> distinct banks

    const int b   = blockIdx.z;
    const int y   = blockIdx.y;
    const int x0  = blockIdx.x * TILE_X;
    const int tid = threadIdx.x;

    const int widx = (b * H + y) * W + x0;

    if (tid < TILE_X) s_win[tid] = g_winner[widx + tid];
    if (tid == 0)     s_n = 0;
    __syncthreads();

    if (tid < TILE_X) {
        int w  = s_win[tid];
        int sl = -1;
        if (w > 0) {
            sl = atomicAdd(&s_n, 1);
            s_pid[sl] = w - 1;
        }
        s_slot[tid] = sl;
    } else if (tid < TILE_X + 32) {
        // restore winner strip to 0 (self-cleaning, replaces the init kernel)
        reinterpret_cast<int4*>(g_winner + widx)[tid - TILE_X] = make_int4(0, 0, 0, 0);
    }
    __syncthreads();

    const int n = s_n;

    // Stage occupied feature rows into smem (coalesced float4 loads).
    const float4* featb4 =
        reinterpret_cast<const float4*>(feat + (size_t)b * P * C);
    for (int i = tid; i < n * (C / 4); i += 256) {
        int sl = i >> 4;          // C/4 == 16
        int q  = i & 15;
        float4 v = __ldg(&featb4[(size_t)s_pid[sl] * (C / 4) + q]);
        float* dst = &s_feat[sl * 65 + q * 4];
        dst[0] = v.x; dst[1] = v.y; dst[2] = v.z; dst[3] = v.w;
    }
    __syncthreads();

    // Emission: warp wq handles channel c = it*8 + wq, lane = x-quad.
    const int lane = tid & 31;
    const int wq   = tid >> 5;
    const size_t c_stride_q = (size_t)H * W / 4;
    const size_t out_q_base = ((((size_t)b * C) * H + y) * W + x0) / 4;
    float4* out4 = reinterpret_cast<float4*>(out);

    const int x4 = lane * 4;
    const int s0 = s_slot[x4 + 0];
    const int s1 = s_slot[x4 + 1];
    const int s2 = s_slot[x4 + 2];
    const int s3 = s_slot[x4 + 3];

    #pragma unroll
    for (int it = 0; it < 8; ++it) {
        const int c = it * 8 + wq;
        float4 v;
        v.x = (s0 >= 0) ? s_feat[s0 * 65 + c] : 0.0f;
        v.y = (s1 >= 0) ? s_feat[s1 * 65 + c] : 0.0f;
        v.z = (s2 >= 0) ? s_feat[s2 * 65 + c] : 0.0f;
        v.w = (s3 >= 0) ? s_feat[s3 * 65 + c] : 0.0f;
        __stcs(&out4[out_q_base + (size_t)c * c_stride_q + lane], v);
    }
}

extern "C" void kernel_launch(void* const* d_in, const int* in_sizes, int n_in,
                              void* d_out, int out_size) {
    const float* feat   = (const float*)d_in[0];   // [B, P, C] fp32
    const int*   coords = (const int*)d_in[1];     // [B, P, 4] int32
    float* out = (float*)d_out;                    // [B, C, H, W] fp32

    scatter_winner_kernel<<<(B * P + 255) / 256, 256>>>(coords);

    dim3 grid(W / TILE_X, H, B);   // (4, 512, 4) = 8192 blocks
    gather_out_kernel<<<grid, 256>>>(feat, out);
}